// round 12
// baseline (speedup 1.0000x reference)
#include <cuda_runtime.h>
#include <math.h>

#define TT 4
#define NN 50000
#define EE 400000
#define CAP 2048
#define NSLOT 8
#define NCOPY 8
#define SBLK 196   // scan blocks per t (196*256 >= NN)

typedef unsigned long long ull;

// ---------------- scratch ----------------
__device__ float g_XW0[TT * NN * 128];
__device__ float g_X1[TT * NN * 128];
__device__ float g_XW1[TT * NN * 64];
__device__ float g_scores[NSLOT * NN];
__device__ unsigned g_hist[NSLOT * NCOPY * 4096];
__device__ int g_ctrl[NSLOT * 4];
__device__ ull g_cand[NSLOT * CAP];
__device__ int g_tidx[NSLOT * 128];
__device__ float g_ttanh[NSLOT * 128];
__device__ float g_zT[NSLOT * 128 * 128];   // zT[slot][i][c] (transposed)
__device__ float g_Q0snap[TT * 128 * 128];
__device__ float g_Q1snap[TT * 128 * 64];
__device__ float g_snorm[2];
__device__ int g_cnt[TT * NN];
__device__ int g_off[TT * (NN + 1)];
__device__ int g_bsum[TT * SBLK];
__device__ ull g_epack[TT * EE];   // packed (weight_bits<<32 | src)

__device__ __forceinline__ unsigned mono(float f) {
    unsigned u = __float_as_uint(f);
    return (u & 0x80000000u) ? ~u : (u | 0x80000000u);
}
__device__ __forceinline__ float sigm(float x) { return 1.f / (1.f + expf(-x)); }
__device__ __forceinline__ ull fdup(float v) {
    ull r; asm("mov.b64 %0, {%1,%2};" : "=l"(r) : "f"(v), "f"(v)); return r;
}
__device__ __forceinline__ void ffma2(ull& d, ull a, ull b) {
    asm("fma.rn.f32x2 %0, %1, %2, %3;" : "=l"(d) : "l"(a), "l"(b), "l"(d));
}
__device__ __forceinline__ float2 up2(ull v) {
    float2 f; asm("mov.b64 {%0,%1}, %2;" : "=f"(f.x), "=f"(f.y) : "l"(v)); return f;
}

// ---------------- init ----------------
__global__ void k_snorm(const float* __restrict__ s0, const float* __restrict__ s1,
                        float* out) {
    __shared__ float sh[128];
    const float* sc = blockIdx.x ? s1 : s0;
    int t = threadIdx.x;
    float v = sc[t];
    sh[t] = v * v;
    __syncthreads();
    for (int o = 64; o > 0; o >>= 1) {
        if (t < o) sh[t] += sh[t + o];
        __syncthreads();
    }
    if (t == 0) out[blockIdx.x] = sqrtf(sh[0]);
}

__global__ void k_zeroall(unsigned* hist, int* ctrl, int* cnt) {
    int i = blockIdx.x * blockDim.x + threadIdx.x;
    if (i < NSLOT * NCOPY * 4096) hist[i] = 0u;
    if (i < NSLOT * 4) ctrl[i] = 0;
    if (i < TT * NN) cnt[i] = 0;
}

// ---------------- scores + replicated histogram (layer0) ----------------
__global__ void k_scoreshist(const float* __restrict__ Xb,
                             const float* __restrict__ maskb,
                             const float* __restrict__ scorer,
                             const float* __restrict__ snormp,
                             float* __restrict__ scores, unsigned* __restrict__ hist) {
    int slot = blockIdx.y;
    const float4* X4 = (const float4*)(Xb + (size_t)slot * NN * 128);
    const float* m = maskb + (size_t)slot * NN;
    int gt = blockIdx.x * blockDim.x + threadIdx.x;
    int n = gt >> 5, lane = gt & 31;
    if (n >= NN) return;
    float4 x = __ldg(&X4[(size_t)n * 32 + lane]);
    float4 s4 = __ldg(&((const float4*)scorer)[lane]);
    float acc = x.x * s4.x + x.y * s4.y + x.z * s4.z + x.w * s4.w;
#pragma unroll
    for (int o = 16; o; o >>= 1) acc += __shfl_xor_sync(0xffffffffu, acc, o);
    if (lane == 0) {
        float s = acc / (*snormp) + m[n];
        scores[slot * NN + n] = s;
        int cp = blockIdx.x & (NCOPY - 1);
        atomicAdd(&hist[slot * NCOPY * 4096 + cp * 4096 + (mono(s) >> 20)], 1u);
    }
}

// findbucket: sums NCOPY replicated histograms per bucket
__global__ void k_findbucket(const unsigned* __restrict__ hist, int* __restrict__ ctrl,
                             int slot0, int k) {
    __shared__ unsigned sh[1024];
    int slot = slot0 + blockIdx.x;
    const unsigned* h = hist + (size_t)slot * NCOPY * 4096;
    int tid = threadIdx.x;
    int c0 = tid * 4;
    unsigned h0 = 0, h1 = 0, h2 = 0, h3 = 0;
#pragma unroll
    for (int cp = 0; cp < NCOPY; cp++) {
        const unsigned* hc = h + cp * 4096;
        h0 += hc[c0]; h1 += hc[c0 + 1]; h2 += hc[c0 + 2]; h3 += hc[c0 + 3];
    }
    sh[tid] = h0 + h1 + h2 + h3;
    __syncthreads();
    for (int o = 1; o < 1024; o <<= 1) {
        unsigned v = (tid + o < 1024) ? sh[tid + o] : 0u;
        __syncthreads();
        sh[tid] += v;
        __syncthreads();
    }
    unsigned above = (tid < 1023) ? sh[tid + 1] : 0u;
    unsigned hh[4] = {h0, h1, h2, h3};
    for (int b = 3; b >= 0; --b) {
        unsigned cnt = hh[b];
        if (above < (unsigned)k && above + cnt >= (unsigned)k) ctrl[slot * 4 + 0] = c0 + b;
        above += cnt;
    }
}

__global__ void k_compact(const float* __restrict__ scores, int* __restrict__ ctrl,
                          ull* __restrict__ cand, int slot0) {
    int slot = slot0 + blockIdx.y;
    int bstar = ctrl[slot * 4 + 0];
    int i = blockIdx.x * blockDim.x + threadIdx.x;
    if (i >= NN) return;
    unsigned key = mono(scores[slot * NN + i]);
    if ((int)(key >> 20) >= bstar) {
        int p = atomicAdd(&ctrl[slot * 4 + 2], 1);
        if (p < CAP)
            cand[slot * CAP + p] = ((ull)key << 32) | (ull)(0xFFFFFFFFu - (unsigned)i);
    }
}

__global__ void k_sortselect(const float* __restrict__ scores, const ull* __restrict__ cand,
                             const int* __restrict__ ctrl, int* __restrict__ tidx,
                             float* __restrict__ ttanh, int slot0, int k) {
    __shared__ ull s[CAP];
    int slot = slot0 + blockIdx.x;
    int tid = threadIdx.x;
    int n = ctrl[slot * 4 + 2];
    if (n > CAP) n = CAP;
    for (int i = tid; i < CAP; i += 1024) s[i] = (i < n) ? cand[slot * CAP + i] : 0ULL;
    __syncthreads();
    for (int size = 2; size <= CAP; size <<= 1)
        for (int stride = size >> 1; stride > 0; stride >>= 1) {
            for (int i = tid; i < CAP; i += 1024) {
                int j = i ^ stride;
                if (j > i) {
                    ull a = s[i], b = s[j];
                    bool desc = ((i & size) == 0);
                    if (desc ? (a < b) : (a > b)) { s[i] = b; s[j] = a; }
                }
            }
            __syncthreads();
        }
    if (tid < k) {
        ull c = s[tid];
        unsigned idx = 0xFFFFFFFFu - (unsigned)(c & 0xFFFFFFFFu);
        tidx[slot * 128 + tid] = (int)idx;
        ttanh[slot * 128 + tid] = tanhf(scores[slot * NN + idx]);
    }
}

// buildz: writes TRANSPOSED z: zT[slot][r][j], r=thread, j=block (COLS=gridDim.x)
__global__ void k_buildz(const float* __restrict__ Xb,
                         const int* __restrict__ tidx, const float* __restrict__ ttanh,
                         float* __restrict__ zT, int slot0) {
    int by = blockIdx.y;
    int slot = slot0 + by;
    const float* X = Xb + (size_t)by * NN * 128;
    int j = blockIdx.x, r = threadIdx.x;
    int COLS = gridDim.x;
    zT[slot * 16384 + r * COLS + j] =
        X[(size_t)tidx[slot * 128 + j] * 128 + r] * ttanh[slot * 128 + j];
}

// ---------------- GRU: all t fused, coalesced (block = 32 columns resident) ----------------
// threads: 1024 = 32 cols (lane) x 32 row-chunk; 4 passes cover 128 rows.
// W[r][i]: warp-broadcast (whole warp shares r). zT/Q/B/rstq: lane-contiguous.
template <int COLS>
__global__ void __launch_bounds__(1024) k_gruallc(
    const float* __restrict__ Wu, const float* __restrict__ Uu,
    const float* __restrict__ Bu, const float* __restrict__ Wr,
    const float* __restrict__ Ur, const float* __restrict__ Br,
    const float* __restrict__ Wh, const float* __restrict__ Uh,
    const float* __restrict__ Bh, const float* __restrict__ zb,
    const float* __restrict__ Qinit, float* __restrict__ Qsnap) {
    __shared__ float s_z[128][32];
    __shared__ float s_q[128][32];
    __shared__ float s_rstq[128][32];
    int tid = threadIdx.x;
    int cl = tid & 31, rq = tid >> 5;
    int c = blockIdx.x * 32 + cl;
#pragma unroll
    for (int p = 0; p < 4; p++) {
        int i = rq + p * 32;
        s_q[i][cl] = __ldg(&Qinit[i * COLS + c]);
    }
    for (int t = 0; t < TT; t++) {
        const float* z = zb + t * 16384;
#pragma unroll
        for (int p = 0; p < 4; p++) {
            int i = rq + p * 32;
            s_z[i][cl] = __ldg(&z[i * COLS + c]);
        }
        __syncthreads();
        float u_reg[4], q_reg[4];
#pragma unroll
        for (int p = 0; p < 4; p++) {
            int r = rq + p * 32;
            float su = 0, sr = 0, qu = 0, qr = 0;
#pragma unroll 4
            for (int i = 0; i < 128; i++) {
                float zi = s_z[i][cl], qi = s_q[i][cl];
                su += __ldg(&Wu[r * 128 + i]) * zi;
                sr += __ldg(&Wr[r * 128 + i]) * zi;
                qu += __ldg(&Uu[r * 128 + i]) * qi;
                qr += __ldg(&Ur[r * 128 + i]) * qi;
            }
            float u = sigm(su + qu + Bu[r * COLS + c]);
            float rs = sigm(sr + qr + Br[r * COLS + c]);
            u_reg[p] = u;
            q_reg[p] = s_q[r][cl];
            s_rstq[r][cl] = rs * q_reg[p];
        }
        __syncthreads();
#pragma unroll
        for (int p = 0; p < 4; p++) {
            int r = rq + p * 32;
            float h = 0;
#pragma unroll 4
            for (int i = 0; i < 128; i++) {
                h += __ldg(&Wh[r * 128 + i]) * s_z[i][cl];
                h += __ldg(&Uh[r * 128 + i]) * s_rstq[i][cl];
            }
            float hc = tanhf(h + Bh[r * COLS + c]);
            float u = u_reg[p];
            float qn = (1.f - u) * q_reg[p] + u * hc;
            Qsnap[t * 128 * COLS + r * COLS + c] = qn;
            s_q[r][cl] = qn;
        }
        __syncthreads();
    }
}

// ---------------- SGEMM (f32x2, conflict-free strided micro-tile) ----------------
template <int BN>
__device__ __forceinline__ void gemm_tile(const float* __restrict__ A, bool aok, int lr,
                                          int lk, const float* __restrict__ B,
                                          float* __restrict__ C, int row0, int tx, int ty,
                                          float* As_f, ull* Bs, int tid) {
    constexpr int TN = BN / 16;
    ull* As = (ull*)As_f;
    ull acc[4][TN];
#pragma unroll
    for (int mp = 0; mp < 4; mp++)
#pragma unroll
        for (int n = 0; n < TN; n++) acc[mp][n] = 0ULL;
    const float4 z4 = make_float4(0.f, 0.f, 0.f, 0.f);
    int kb = tid >> 4, jj = tid & 15;
    for (int kt = 0; kt < 8; kt++) {
        float4 a0 = aok ? *(const float4*)(A + (size_t)(row0 + lr) * 128 + kt * 16 + lk) : z4;
        float4 a1 = aok ? *(const float4*)(A + (size_t)(row0 + lr) * 128 + kt * 16 + lk + 4) : z4;
        float av[8] = {a0.x, a0.y, a0.z, a0.w, a1.x, a1.y, a1.z, a1.w};
#pragma unroll
        for (int q = 0; q < 8; q++) As_f[(lk + q) * 128 + lr] = av[q];
#pragma unroll
        for (int i = 0; i < TN; i++) {
            float bv = B[(size_t)(kt * 16 + kb) * BN + jj + 16 * i];
            Bs[kb * BN + jj + 16 * i] = fdup(bv);
        }
        __syncthreads();
#pragma unroll
        for (int kk = 0; kk < 16; kk++) {
            ull a[4], rb[TN];
#pragma unroll
            for (int mp = 0; mp < 4; mp++) a[mp] = As[kk * 64 + ty + 16 * mp];
#pragma unroll
            for (int n = 0; n < TN; n++) rb[n] = Bs[kk * BN + tx + 16 * n];
#pragma unroll
            for (int mp = 0; mp < 4; mp++)
#pragma unroll
                for (int n = 0; n < TN; n++) ffma2(acc[mp][n], a[mp], rb[n]);
        }
        __syncthreads();
    }
#pragma unroll
    for (int mp = 0; mp < 4; mp++) {
        int r = row0 + 2 * (ty + 16 * mp);
        if (r >= NN) continue;
#pragma unroll
        for (int n = 0; n < TN; n++) {
            float2 p = up2(acc[mp][n]);
            C[(size_t)r * BN + tx + 16 * n] = p.x;
            C[(size_t)(r + 1) * BN + tx + 16 * n] = p.y;
        }
    }
}

template <int BN>
__global__ void __launch_bounds__(256) k_gemmcf(const float* __restrict__ Ab, size_t astr,
                                                const float* __restrict__ Bb, size_t bstr,
                                                float* __restrict__ Cb, size_t cstr) {
    __shared__ float As_f[16 * 128];
    __shared__ ull Bs[16 * BN];
    const float* A = Ab + (size_t)blockIdx.y * astr;
    const float* B = Bb + (size_t)blockIdx.y * bstr;
    float* C = Cb + (size_t)blockIdx.y * cstr;
    int tid = threadIdx.x, tx = tid & 15, ty = tid >> 4;
    int row0 = blockIdx.x * 128;
    int lr = tid >> 1, lk = (tid & 1) * 8;
    bool aok = (row0 + lr) < NN;
    gemm_tile<BN>(A, aok, lr, lk, B, C, row0, tx, ty, As_f, Bs, tid);
}

// ---------------- CSR build ----------------
__global__ void k_histdst(const int* __restrict__ dstb, int* __restrict__ cnt) {
    int t = blockIdx.y;
    int e = blockIdx.x * blockDim.x + threadIdx.x;
    if (e < EE) atomicAdd(&cnt[t * NN + dstb[(size_t)t * EE + e]], 1);
}

__global__ void k_scan1(int* __restrict__ cnt, int* __restrict__ off,
                        int* __restrict__ bsum) {
    __shared__ int ws[8];
    int t = blockIdx.y, b = blockIdx.x;
    int tid = threadIdx.x, lane = tid & 31, wid = tid >> 5;
    int i = b * 256 + tid;
    int c = (i < NN) ? cnt[t * NN + i] : 0;
    if (i < NN) cnt[t * NN + i] = 0;
    int v = c;
#pragma unroll
    for (int o = 1; o < 32; o <<= 1) {
        int nv = __shfl_up_sync(0xffffffffu, v, o);
        if (lane >= o) v += nv;
    }
    if (lane == 31) ws[wid] = v;
    __syncthreads();
    if (wid == 0 && lane < 8) {
        int w = ws[lane];
#pragma unroll
        for (int o = 1; o < 8; o <<= 1) {
            int nw = __shfl_up_sync(0xFFu, w, o);
            if (lane >= o) w += nw;
        }
        ws[lane] = w;
    }
    __syncthreads();
    int ex = v - c + (wid ? ws[wid - 1] : 0);
    if (i < NN) off[t * (NN + 1) + i] = ex;
    if (tid == 255) bsum[t * SBLK + b] = ex + c;
}

__global__ void k_scan2(int* __restrict__ bsum, int* __restrict__ off) {
    __shared__ int ws[8];
    int t = blockIdx.x;
    int tid = threadIdx.x, lane = tid & 31, wid = tid >> 5;
    int c = (tid < SBLK) ? bsum[t * SBLK + tid] : 0;
    int v = c;
#pragma unroll
    for (int o = 1; o < 32; o <<= 1) {
        int nv = __shfl_up_sync(0xffffffffu, v, o);
        if (lane >= o) v += nv;
    }
    if (lane == 31) ws[wid] = v;
    __syncthreads();
    if (wid == 0 && lane < 8) {
        int w = ws[lane];
#pragma unroll
        for (int o = 1; o < 8; o <<= 1) {
            int nw = __shfl_up_sync(0xFFu, w, o);
            if (lane >= o) w += nw;
        }
        ws[lane] = w;
    }
    __syncthreads();
    int ex = v - c + (wid ? ws[wid - 1] : 0);
    if (tid < SBLK) bsum[t * SBLK + tid] = ex;
    if (tid == SBLK - 1) off[t * (NN + 1) + NN] = ex + c;
}

__global__ void k_scan3(int* __restrict__ off, const int* __restrict__ bsum) {
    int t = blockIdx.y, b = blockIdx.x;
    int i = b * 256 + threadIdx.x;
    if (i < NN) off[t * (NN + 1) + i] += bsum[t * SBLK + b];
}

// place: ONE packed 8B scatter per edge
__global__ void k_place(const int* __restrict__ srcb, const int* __restrict__ dstb,
                        const float* __restrict__ wb, int* __restrict__ cntb,
                        const int* __restrict__ offb, ull* __restrict__ epack) {
    int t = blockIdx.y;
    int e = blockIdx.x * blockDim.x + threadIdx.x;
    if (e >= EE) return;
    int d = dstb[(size_t)t * EE + e];
    int p = offb[t * (NN + 1) + d] + atomicAdd(&cntb[t * NN + d], 1);
    ull pk = ((ull)__float_as_uint(wb[(size_t)t * EE + e]) << 32) |
             (ull)(unsigned)srcb[(size_t)t * EE + e];
    epack[(size_t)t * EE + p] = pk;
}

// ---------------- SpMM (batched over T) + fused layer1 scores ----------------
__global__ void k_spmm128(const float* __restrict__ XWb,
                          const ull* __restrict__ epb,
                          const int* __restrict__ offb, float* __restrict__ outb,
                          const float* __restrict__ scorer,
                          const float* __restrict__ snormp,
                          const float* __restrict__ maskb,
                          float* __restrict__ scores, unsigned* __restrict__ hist,
                          int slot0) {
    int t = blockIdx.y;
    int slot = slot0 + t;
    const float4* X4 = (const float4*)(XWb + (size_t)t * NN * 128);
    const ull* ep = epb + (size_t)t * EE;
    const int* off = offb + t * (NN + 1);
    float* out = outb + (size_t)t * NN * 128;
    int gt = blockIdx.x * blockDim.x + threadIdx.x;
    int n = gt >> 5, lane = gt & 31;
    if (n >= NN) return;
    int beg = off[n], end = off[n + 1];
    float4 a0 = make_float4(0.f, 0.f, 0.f, 0.f);
    float4 a1 = a0, a2 = a0, a3 = a0;
    int j = beg;
    for (; j + 4 <= end; j += 4) {
        ull e0 = __ldg(ep + j), e1 = __ldg(ep + j + 1);
        ull e2 = __ldg(ep + j + 2), e3 = __ldg(ep + j + 3);
        int s0 = (int)(unsigned)e0, s1 = (int)(unsigned)e1;
        int s2 = (int)(unsigned)e2, s3 = (int)(unsigned)e3;
        float w0 = __uint_as_float((unsigned)(e0 >> 32));
        float w1 = __uint_as_float((unsigned)(e1 >> 32));
        float w2 = __uint_as_float((unsigned)(e2 >> 32));
        float w3 = __uint_as_float((unsigned)(e3 >> 32));
        float4 v0 = __ldg(&X4[(size_t)s0 * 32 + lane]);
        float4 v1 = __ldg(&X4[(size_t)s1 * 32 + lane]);
        float4 v2 = __ldg(&X4[(size_t)s2 * 32 + lane]);
        float4 v3 = __ldg(&X4[(size_t)s3 * 32 + lane]);
        a0.x += v0.x * w0; a0.y += v0.y * w0; a0.z += v0.z * w0; a0.w += v0.w * w0;
        a1.x += v1.x * w1; a1.y += v1.y * w1; a1.z += v1.z * w1; a1.w += v1.w * w1;
        a2.x += v2.x * w2; a2.y += v2.y * w2; a2.z += v2.z * w2; a2.w += v2.w * w2;
        a3.x += v3.x * w3; a3.y += v3.y * w3; a3.z += v3.z * w3; a3.w += v3.w * w3;
    }
    for (; j < end; ++j) {
        ull e0 = __ldg(ep + j);
        int s = (int)(unsigned)e0;
        float wt = __uint_as_float((unsigned)(e0 >> 32));
        float4 v = __ldg(&X4[(size_t)s * 32 + lane]);
        a0.x += v.x * wt; a0.y += v.y * wt; a0.z += v.z * wt; a0.w += v.w * wt;
    }
    float4 a = make_float4((a0.x + a1.x) + (a2.x + a3.x), (a0.y + a1.y) + (a2.y + a3.y),
                           (a0.z + a1.z) + (a2.z + a3.z), (a0.w + a1.w) + (a2.w + a3.w));
    float4 r = make_float4(fmaxf(a.x, 0.f), fmaxf(a.y, 0.f), fmaxf(a.z, 0.f), fmaxf(a.w, 0.f));
    ((float4*)out)[(size_t)n * 32 + lane] = r;
    float4 sc4 = __ldg(&((const float4*)scorer)[lane]);
    float sc = r.x * sc4.x + r.y * sc4.y + r.z * sc4.z + r.w * sc4.w;
#pragma unroll
    for (int o = 16; o; o >>= 1) sc += __shfl_xor_sync(0xffffffffu, sc, o);
    if (lane == 0) {
        float s = sc / (*snormp) + maskb[(size_t)t * NN + n];
        scores[slot * NN + n] = s;
        int cp = blockIdx.x & (NCOPY - 1);
        atomicAdd(&hist[slot * NCOPY * 4096 + cp * 4096 + (mono(s) >> 20)], 1u);
    }
}

__global__ void k_spmm64(const float* __restrict__ XWb, const ull* __restrict__ epb,
                         const int* __restrict__ offb, float* __restrict__ outb) {
    int t = blockIdx.y;
    const float2* X2 = (const float2*)(XWb + (size_t)t * NN * 64);
    const ull* ep = epb + (size_t)t * EE;
    const int* off = offb + t * (NN + 1);
    float* out = outb + (size_t)t * NN * 64;
    int gt = blockIdx.x * blockDim.x + threadIdx.x;
    int n = gt >> 5, lane = gt & 31;
    if (n >= NN) return;
    int beg = off[n], end = off[n + 1];
    float2 a0 = make_float2(0.f, 0.f), a1 = a0, a2 = a0, a3 = a0;
    int j = beg;
    for (; j + 4 <= end; j += 4) {
        ull e0 = __ldg(ep + j), e1 = __ldg(ep + j + 1);
        ull e2 = __ldg(ep + j + 2), e3 = __ldg(ep + j + 3);
        int s0 = (int)(unsigned)e0, s1 = (int)(unsigned)e1;
        int s2 = (int)(unsigned)e2, s3 = (int)(unsigned)e3;
        float w0 = __uint_as_float((unsigned)(e0 >> 32));
        float w1 = __uint_as_float((unsigned)(e1 >> 32));
        float w2 = __uint_as_float((unsigned)(e2 >> 32));
        float w3 = __uint_as_float((unsigned)(e3 >> 32));
        float2 v0 = __ldg(&X2[(size_t)s0 * 32 + lane]);
        float2 v1 = __ldg(&X2[(size_t)s1 * 32 + lane]);
        float2 v2 = __ldg(&X2[(size_t)s2 * 32 + lane]);
        float2 v3 = __ldg(&X2[(size_t)s3 * 32 + lane]);
        a0.x += v0.x * w0; a0.y += v0.y * w0;
        a1.x += v1.x * w1; a1.y += v1.y * w1;
        a2.x += v2.x * w2; a2.y += v2.y * w2;
        a3.x += v3.x * w3; a3.y += v3.y * w3;
    }
    for (; j < end; ++j) {
        ull e0 = __ldg(ep + j);
        int s = (int)(unsigned)e0;
        float wt = __uint_as_float((unsigned)(e0 >> 32));
        float2 v = __ldg(&X2[(size_t)s * 32 + lane]);
        a0.x += v.x * wt; a0.y += v.y * wt;
    }
    float2 a = make_float2((a0.x + a1.x) + (a2.x + a3.x), (a0.y + a1.y) + (a2.y + a3.y));
    ((float2*)out)[(size_t)n * 32 + lane] = make_float2(fmaxf(a.x, 0.f), fmaxf(a.y, 0.f));
}

// ---------------- host orchestration ----------------
extern "C" void kernel_launch(void* const* d_in, const int* in_sizes, int n_in,
                              void* d_out, int out_size) {
    const float* node_embs = (const float*)d_in[0];
    const float* mask = (const float*)d_in[1];
    const int* esrc = (const int*)d_in[2];
    const int* edst = (const int*)d_in[3];
    const float* ew = (const float*)d_in[4];
    const float* w0 = (const float*)d_in[5];
    const float* w1 = (const float*)d_in[6];
    const float* p0[10];
    const float* p1[10];
    for (int i = 0; i < 10; i++) p0[i] = (const float*)d_in[7 + i];
    for (int i = 0; i < 10; i++) p1[i] = (const float*)d_in[17 + i];
    float* out = (float*)d_out;

    float *XW0, *X1, *XW1, *scores, *ttanh, *zT, *Q0s, *Q1s, *snorm;
    unsigned* hist;
    int *ctrl, *tidx, *cnt, *off, *bsum;
    ull *cand, *epack;
    cudaGetSymbolAddress((void**)&XW0, g_XW0);
    cudaGetSymbolAddress((void**)&X1, g_X1);
    cudaGetSymbolAddress((void**)&XW1, g_XW1);
    cudaGetSymbolAddress((void**)&scores, g_scores);
    cudaGetSymbolAddress((void**)&hist, g_hist);
    cudaGetSymbolAddress((void**)&ctrl, g_ctrl);
    cudaGetSymbolAddress((void**)&cand, g_cand);
    cudaGetSymbolAddress((void**)&tidx, g_tidx);
    cudaGetSymbolAddress((void**)&ttanh, g_ttanh);
    cudaGetSymbolAddress((void**)&zT, g_zT);
    cudaGetSymbolAddress((void**)&Q0s, g_Q0snap);
    cudaGetSymbolAddress((void**)&Q1s, g_Q1snap);
    cudaGetSymbolAddress((void**)&snorm, g_snorm);
    cudaGetSymbolAddress((void**)&cnt, g_cnt);
    cudaGetSymbolAddress((void**)&off, g_off);
    cudaGetSymbolAddress((void**)&bsum, g_bsum);
    cudaGetSymbolAddress((void**)&epack, g_epack);

    const int NBLK = (NN + 255) / 256;
    const int WBLK = (NN * 32 + 255) / 256;
    const int EBLK = (EE + 255) / 256;
    const int GBLK = (NN + 127) / 128;
    const int ZBLK = (NSLOT * NCOPY * 4096 + 255) / 256;

    k_snorm<<<2, 128>>>(p0[9], p1[9], snorm);
    k_zeroall<<<ZBLK, 256>>>(hist, ctrl, cnt);
    k_histdst<<<dim3(EBLK, TT), 256>>>(edst, cnt);
    k_scoreshist<<<dim3(WBLK, TT), 256>>>(node_embs, mask, p0[9], snorm + 0, scores, hist);
    k_scan1<<<dim3(SBLK, TT), 256>>>(cnt, off, bsum);
    k_scan2<<<TT, 256>>>(bsum, off);
    k_scan3<<<dim3(SBLK, TT), 256>>>(off, bsum);
    k_place<<<dim3(EBLK, TT), 256>>>(esrc, edst, ew, cnt, off, epack);

    // layer0 top-k (slots 0..3)
    k_findbucket<<<TT, 1024>>>(hist, ctrl, 0, 128);
    k_compact<<<dim3(NBLK, TT), 256>>>(scores, ctrl, cand, 0);
    k_sortselect<<<TT, 1024>>>(scores, cand, ctrl, tidx, ttanh, 0, 128);
    k_buildz<<<dim3(128, TT), 128>>>(node_embs, tidx, ttanh, zT, 0);

    // layer0 GRU: all t fused, coalesced (4 blocks of 32 columns)
    k_gruallc<128><<<4, 1024>>>(p0[0], p0[1], p0[2], p0[3], p0[4], p0[5], p0[6], p0[7],
                                p0[8], zT, w0, Q0s);

    // layer0 GEMM + SpMM (batched over T) with fused layer1 scores
    k_gemmcf<128><<<dim3(GBLK, TT), 256>>>(node_embs, (size_t)NN * 128, Q0s, 16384, XW0,
                                           (size_t)NN * 128);
    k_spmm128<<<dim3(WBLK, TT), 256>>>(XW0, epack, off, X1, p1[9], snorm + 1, mask,
                                       scores, hist, 4);

    // layer1 top-k (slots 4..7)
    k_findbucket<<<TT, 1024>>>(hist, ctrl, 4, 64);
    k_compact<<<dim3(NBLK, TT), 256>>>(scores, ctrl, cand, 4);
    k_sortselect<<<TT, 1024>>>(scores, cand, ctrl, tidx, ttanh, 4, 64);
    k_buildz<<<dim3(64, TT), 128>>>(X1, tidx, ttanh, zT, 4);

    // layer1 GRU: all t fused, coalesced (2 blocks of 32 columns)
    k_gruallc<64><<<2, 1024>>>(p1[0], p1[1], p1[2], p1[3], p1[4], p1[5], p1[6], p1[7],
                               p1[8], zT + 4 * 16384, w1, Q1s);

    // layer1 GEMM + SpMM (batched over T)
    k_gemmcf<64><<<dim3(GBLK, TT), 256>>>(X1, (size_t)NN * 128, Q1s, 8192, XW1,
                                          (size_t)NN * 64);
    k_spmm64<<<dim3(WBLK, TT), 256>>>(XW1, epack, off, out);
}

// round 13
// speedup vs baseline: 1.0089x; 1.0089x over previous
#include <cuda_runtime.h>
#include <math.h>

#define TT 4
#define NN 50000
#define EE 400000
#define CAP 2048
#define NSLOT 8
#define NCOPY 8
#define SBLK 196   // scan blocks per t (196*256 >= NN)

typedef unsigned long long ull;

// ---------------- scratch ----------------
__device__ float g_XW0[TT * NN * 128];
__device__ float g_X1[TT * NN * 128];
__device__ float g_XW1[TT * NN * 64];
__device__ float g_scores[NSLOT * NN];
__device__ unsigned g_hist[NSLOT * NCOPY * 4096];
__device__ int g_ctrl[NSLOT * 4];
__device__ ull g_cand[NSLOT * CAP];
__device__ int g_tidx[NSLOT * 128];
__device__ float g_ttanh[NSLOT * 128];
__device__ float g_zT[NSLOT * 128 * 128];   // zT[slot][i][c] (transposed)
__device__ float g_Q0snap[TT * 128 * 128];
__device__ float g_Q1snap[TT * 128 * 64];
__device__ float g_snorm[2];
__device__ int g_cnt[TT * NN];
__device__ int g_off[TT * (NN + 1)];
__device__ int g_bsum[TT * SBLK];
__device__ ull g_epack[TT * EE];   // packed (weight_bits<<32 | src)

__device__ __forceinline__ unsigned mono(float f) {
    unsigned u = __float_as_uint(f);
    return (u & 0x80000000u) ? ~u : (u | 0x80000000u);
}
__device__ __forceinline__ float sigm(float x) { return 1.f / (1.f + expf(-x)); }
__device__ __forceinline__ ull fdup(float v) {
    ull r; asm("mov.b64 %0, {%1,%2};" : "=l"(r) : "f"(v), "f"(v)); return r;
}
__device__ __forceinline__ void ffma2(ull& d, ull a, ull b) {
    asm("fma.rn.f32x2 %0, %1, %2, %3;" : "=l"(d) : "l"(a), "l"(b), "l"(d));
}
__device__ __forceinline__ float2 up2(ull v) {
    float2 f; asm("mov.b64 {%0,%1}, %2;" : "=f"(f.x), "=f"(f.y) : "l"(v)); return f;
}

// ---------------- init ----------------
__global__ void k_snorm(const float* __restrict__ s0, const float* __restrict__ s1,
                        float* out) {
    __shared__ float sh[128];
    const float* sc = blockIdx.x ? s1 : s0;
    int t = threadIdx.x;
    float v = sc[t];
    sh[t] = v * v;
    __syncthreads();
    for (int o = 64; o > 0; o >>= 1) {
        if (t < o) sh[t] += sh[t + o];
        __syncthreads();
    }
    if (t == 0) out[blockIdx.x] = sqrtf(sh[0]);
}

__global__ void k_zeroall(unsigned* hist, int* ctrl, int* cnt) {
    int i = blockIdx.x * blockDim.x + threadIdx.x;
    if (i < NSLOT * NCOPY * 4096) hist[i] = 0u;
    if (i < NSLOT * 4) ctrl[i] = 0;
    if (i < TT * NN) cnt[i] = 0;
}

// ---------------- scores + replicated histogram (layer0) ----------------
__global__ void k_scoreshist(const float* __restrict__ Xb,
                             const float* __restrict__ maskb,
                             const float* __restrict__ scorer,
                             const float* __restrict__ snormp,
                             float* __restrict__ scores, unsigned* __restrict__ hist) {
    int slot = blockIdx.y;
    const float4* X4 = (const float4*)(Xb + (size_t)slot * NN * 128);
    const float* m = maskb + (size_t)slot * NN;
    int gt = blockIdx.x * blockDim.x + threadIdx.x;
    int n = gt >> 5, lane = gt & 31;
    if (n >= NN) return;
    float4 x = __ldg(&X4[(size_t)n * 32 + lane]);
    float4 s4 = __ldg(&((const float4*)scorer)[lane]);
    float acc = x.x * s4.x + x.y * s4.y + x.z * s4.z + x.w * s4.w;
#pragma unroll
    for (int o = 16; o; o >>= 1) acc += __shfl_xor_sync(0xffffffffu, acc, o);
    if (lane == 0) {
        float s = acc / (*snormp) + m[n];
        scores[slot * NN + n] = s;
        int cp = blockIdx.x & (NCOPY - 1);
        atomicAdd(&hist[slot * NCOPY * 4096 + cp * 4096 + (mono(s) >> 20)], 1u);
    }
}

// findbucket: sums NCOPY replicated histograms per bucket
__global__ void k_findbucket(const unsigned* __restrict__ hist, int* __restrict__ ctrl,
                             int slot0, int k) {
    __shared__ unsigned sh[1024];
    int slot = slot0 + blockIdx.x;
    const unsigned* h = hist + (size_t)slot * NCOPY * 4096;
    int tid = threadIdx.x;
    int c0 = tid * 4;
    unsigned h0 = 0, h1 = 0, h2 = 0, h3 = 0;
#pragma unroll
    for (int cp = 0; cp < NCOPY; cp++) {
        const unsigned* hc = h + cp * 4096;
        h0 += hc[c0]; h1 += hc[c0 + 1]; h2 += hc[c0 + 2]; h3 += hc[c0 + 3];
    }
    sh[tid] = h0 + h1 + h2 + h3;
    __syncthreads();
    for (int o = 1; o < 1024; o <<= 1) {
        unsigned v = (tid + o < 1024) ? sh[tid + o] : 0u;
        __syncthreads();
        sh[tid] += v;
        __syncthreads();
    }
    unsigned above = (tid < 1023) ? sh[tid + 1] : 0u;
    unsigned hh[4] = {h0, h1, h2, h3};
    for (int b = 3; b >= 0; --b) {
        unsigned cnt = hh[b];
        if (above < (unsigned)k && above + cnt >= (unsigned)k) ctrl[slot * 4 + 0] = c0 + b;
        above += cnt;
    }
}

__global__ void k_compact(const float* __restrict__ scores, int* __restrict__ ctrl,
                          ull* __restrict__ cand, int slot0) {
    int slot = slot0 + blockIdx.y;
    int bstar = ctrl[slot * 4 + 0];
    int i = blockIdx.x * blockDim.x + threadIdx.x;
    if (i >= NN) return;
    unsigned key = mono(scores[slot * NN + i]);
    if ((int)(key >> 20) >= bstar) {
        int p = atomicAdd(&ctrl[slot * 4 + 2], 1);
        if (p < CAP)
            cand[slot * CAP + p] = ((ull)key << 32) | (ull)(0xFFFFFFFFu - (unsigned)i);
    }
}

__global__ void k_sortselect(const float* __restrict__ scores, const ull* __restrict__ cand,
                             const int* __restrict__ ctrl, int* __restrict__ tidx,
                             float* __restrict__ ttanh, int slot0, int k) {
    __shared__ ull s[CAP];
    int slot = slot0 + blockIdx.x;
    int tid = threadIdx.x;
    int n = ctrl[slot * 4 + 2];
    if (n > CAP) n = CAP;
    for (int i = tid; i < CAP; i += 1024) s[i] = (i < n) ? cand[slot * CAP + i] : 0ULL;
    __syncthreads();
    for (int size = 2; size <= CAP; size <<= 1)
        for (int stride = size >> 1; stride > 0; stride >>= 1) {
            for (int i = tid; i < CAP; i += 1024) {
                int j = i ^ stride;
                if (j > i) {
                    ull a = s[i], b = s[j];
                    bool desc = ((i & size) == 0);
                    if (desc ? (a < b) : (a > b)) { s[i] = b; s[j] = a; }
                }
            }
            __syncthreads();
        }
    if (tid < k) {
        ull c = s[tid];
        unsigned idx = 0xFFFFFFFFu - (unsigned)(c & 0xFFFFFFFFu);
        tidx[slot * 128 + tid] = (int)idx;
        ttanh[slot * 128 + tid] = tanhf(scores[slot * NN + idx]);
    }
}

// buildz: writes TRANSPOSED z: zT[slot][r][j], r=thread, j=block (COLS=gridDim.x)
__global__ void k_buildz(const float* __restrict__ Xb,
                         const int* __restrict__ tidx, const float* __restrict__ ttanh,
                         float* __restrict__ zT, int slot0) {
    int by = blockIdx.y;
    int slot = slot0 + by;
    const float* X = Xb + (size_t)by * NN * 128;
    int j = blockIdx.x, r = threadIdx.x;
    int COLS = gridDim.x;
    zT[slot * 16384 + r * COLS + j] =
        X[(size_t)tidx[slot * 128 + j] * 128 + r] * ttanh[slot * 128 + j];
}

// ---------------- GRU: all t fused, coalesced (block = 32 columns resident) ----------------
// threads: 1024 = 32 cols (lane) x 32 row-chunk; 4 passes cover 128 rows.
// W[r][i]: warp-broadcast (whole warp shares r). zT/Q/B/rstq: lane-contiguous.
template <int COLS>
__global__ void __launch_bounds__(1024) k_gruallc(
    const float* __restrict__ Wu, const float* __restrict__ Uu,
    const float* __restrict__ Bu, const float* __restrict__ Wr,
    const float* __restrict__ Ur, const float* __restrict__ Br,
    const float* __restrict__ Wh, const float* __restrict__ Uh,
    const float* __restrict__ Bh, const float* __restrict__ zb,
    const float* __restrict__ Qinit, float* __restrict__ Qsnap) {
    __shared__ float s_z[128][32];
    __shared__ float s_q[128][32];
    __shared__ float s_rstq[128][32];
    int tid = threadIdx.x;
    int cl = tid & 31, rq = tid >> 5;
    int c = blockIdx.x * 32 + cl;
#pragma unroll
    for (int p = 0; p < 4; p++) {
        int i = rq + p * 32;
        s_q[i][cl] = __ldg(&Qinit[i * COLS + c]);
    }
    for (int t = 0; t < TT; t++) {
        const float* z = zb + t * 16384;
#pragma unroll
        for (int p = 0; p < 4; p++) {
            int i = rq + p * 32;
            s_z[i][cl] = __ldg(&z[i * COLS + c]);
        }
        __syncthreads();
        float u_reg[4], q_reg[4];
#pragma unroll
        for (int p = 0; p < 4; p++) {
            int r = rq + p * 32;
            float su = 0, sr = 0, qu = 0, qr = 0;
#pragma unroll 4
            for (int i = 0; i < 128; i++) {
                float zi = s_z[i][cl], qi = s_q[i][cl];
                su += __ldg(&Wu[r * 128 + i]) * zi;
                sr += __ldg(&Wr[r * 128 + i]) * zi;
                qu += __ldg(&Uu[r * 128 + i]) * qi;
                qr += __ldg(&Ur[r * 128 + i]) * qi;
            }
            float u = sigm(su + qu + Bu[r * COLS + c]);
            float rs = sigm(sr + qr + Br[r * COLS + c]);
            u_reg[p] = u;
            q_reg[p] = s_q[r][cl];
            s_rstq[r][cl] = rs * q_reg[p];
        }
        __syncthreads();
#pragma unroll
        for (int p = 0; p < 4; p++) {
            int r = rq + p * 32;
            float h = 0;
#pragma unroll 4
            for (int i = 0; i < 128; i++) {
                h += __ldg(&Wh[r * 128 + i]) * s_z[i][cl];
                h += __ldg(&Uh[r * 128 + i]) * s_rstq[i][cl];
            }
            float hc = tanhf(h + Bh[r * COLS + c]);
            float u = u_reg[p];
            float qn = (1.f - u) * q_reg[p] + u * hc;
            Qsnap[t * 128 * COLS + r * COLS + c] = qn;
            s_q[r][cl] = qn;
        }
        __syncthreads();
    }
}

// ---------------- SGEMM (f32x2, conflict-free strided micro-tile) ----------------
template <int BN>
__device__ __forceinline__ void gemm_tile(const float* __restrict__ A, bool aok, int lr,
                                          int lk, const float* __restrict__ B,
                                          float* __restrict__ C, int row0, int tx, int ty,
                                          float* As_f, ull* Bs, int tid) {
    constexpr int TN = BN / 16;
    ull* As = (ull*)As_f;
    ull acc[4][TN];
#pragma unroll
    for (int mp = 0; mp < 4; mp++)
#pragma unroll
        for (int n = 0; n < TN; n++) acc[mp][n] = 0ULL;
    const float4 z4 = make_float4(0.f, 0.f, 0.f, 0.f);
    int kb = tid >> 4, jj = tid & 15;
    for (int kt = 0; kt < 8; kt++) {
        float4 a0 = aok ? *(const float4*)(A + (size_t)(row0 + lr) * 128 + kt * 16 + lk) : z4;
        float4 a1 = aok ? *(const float4*)(A + (size_t)(row0 + lr) * 128 + kt * 16 + lk + 4) : z4;
        float av[8] = {a0.x, a0.y, a0.z, a0.w, a1.x, a1.y, a1.z, a1.w};
#pragma unroll
        for (int q = 0; q < 8; q++) As_f[(lk + q) * 128 + lr] = av[q];
#pragma unroll
        for (int i = 0; i < TN; i++) {
            float bv = B[(size_t)(kt * 16 + kb) * BN + jj + 16 * i];
            Bs[kb * BN + jj + 16 * i] = fdup(bv);
        }
        __syncthreads();
#pragma unroll
        for (int kk = 0; kk < 16; kk++) {
            ull a[4], rb[TN];
#pragma unroll
            for (int mp = 0; mp < 4; mp++) a[mp] = As[kk * 64 + ty + 16 * mp];
#pragma unroll
            for (int n = 0; n < TN; n++) rb[n] = Bs[kk * BN + tx + 16 * n];
#pragma unroll
            for (int mp = 0; mp < 4; mp++)
#pragma unroll
                for (int n = 0; n < TN; n++) ffma2(acc[mp][n], a[mp], rb[n]);
        }
        __syncthreads();
    }
#pragma unroll
    for (int mp = 0; mp < 4; mp++) {
        int r = row0 + 2 * (ty + 16 * mp);
        if (r >= NN) continue;
#pragma unroll
        for (int n = 0; n < TN; n++) {
            float2 p = up2(acc[mp][n]);
            C[(size_t)r * BN + tx + 16 * n] = p.x;
            C[(size_t)(r + 1) * BN + tx + 16 * n] = p.y;
        }
    }
}

template <int BN>
__global__ void __launch_bounds__(256) k_gemmcf(const float* __restrict__ Ab, size_t astr,
                                                const float* __restrict__ Bb, size_t bstr,
                                                float* __restrict__ Cb, size_t cstr) {
    __shared__ float As_f[16 * 128];
    __shared__ ull Bs[16 * BN];
    const float* A = Ab + (size_t)blockIdx.y * astr;
    const float* B = Bb + (size_t)blockIdx.y * bstr;
    float* C = Cb + (size_t)blockIdx.y * cstr;
    int tid = threadIdx.x, tx = tid & 15, ty = tid >> 4;
    int row0 = blockIdx.x * 128;
    int lr = tid >> 1, lk = (tid & 1) * 8;
    bool aok = (row0 + lr) < NN;
    gemm_tile<BN>(A, aok, lr, lk, B, C, row0, tx, ty, As_f, Bs, tid);
}

// ---------------- CSR build ----------------
__global__ void k_histdst(const int* __restrict__ dstb, int* __restrict__ cnt) {
    int t = blockIdx.y;
    int e = blockIdx.x * blockDim.x + threadIdx.x;
    if (e < EE) atomicAdd(&cnt[t * NN + dstb[(size_t)t * EE + e]], 1);
}

__global__ void k_scan1(int* __restrict__ cnt, int* __restrict__ off,
                        int* __restrict__ bsum) {
    __shared__ int ws[8];
    int t = blockIdx.y, b = blockIdx.x;
    int tid = threadIdx.x, lane = tid & 31, wid = tid >> 5;
    int i = b * 256 + tid;
    int c = (i < NN) ? cnt[t * NN + i] : 0;
    if (i < NN) cnt[t * NN + i] = 0;
    int v = c;
#pragma unroll
    for (int o = 1; o < 32; o <<= 1) {
        int nv = __shfl_up_sync(0xffffffffu, v, o);
        if (lane >= o) v += nv;
    }
    if (lane == 31) ws[wid] = v;
    __syncthreads();
    if (wid == 0 && lane < 8) {
        int w = ws[lane];
#pragma unroll
        for (int o = 1; o < 8; o <<= 1) {
            int nw = __shfl_up_sync(0xFFu, w, o);
            if (lane >= o) w += nw;
        }
        ws[lane] = w;
    }
    __syncthreads();
    int ex = v - c + (wid ? ws[wid - 1] : 0);
    if (i < NN) off[t * (NN + 1) + i] = ex;
    if (tid == 255) bsum[t * SBLK + b] = ex + c;
}

__global__ void k_scan2(int* __restrict__ bsum, int* __restrict__ off) {
    __shared__ int ws[8];
    int t = blockIdx.x;
    int tid = threadIdx.x, lane = tid & 31, wid = tid >> 5;
    int c = (tid < SBLK) ? bsum[t * SBLK + tid] : 0;
    int v = c;
#pragma unroll
    for (int o = 1; o < 32; o <<= 1) {
        int nv = __shfl_up_sync(0xffffffffu, v, o);
        if (lane >= o) v += nv;
    }
    if (lane == 31) ws[wid] = v;
    __syncthreads();
    if (wid == 0 && lane < 8) {
        int w = ws[lane];
#pragma unroll
        for (int o = 1; o < 8; o <<= 1) {
            int nw = __shfl_up_sync(0xFFu, w, o);
            if (lane >= o) w += nw;
        }
        ws[lane] = w;
    }
    __syncthreads();
    int ex = v - c + (wid ? ws[wid - 1] : 0);
    if (tid < SBLK) bsum[t * SBLK + tid] = ex;
    if (tid == SBLK - 1) off[t * (NN + 1) + NN] = ex + c;
}

__global__ void k_scan3(int* __restrict__ off, const int* __restrict__ bsum) {
    int t = blockIdx.y, b = blockIdx.x;
    int i = b * 256 + threadIdx.x;
    if (i < NN) off[t * (NN + 1) + i] += bsum[t * SBLK + b];
}

// place: ONE packed 8B scatter per edge
__global__ void k_place(const int* __restrict__ srcb, const int* __restrict__ dstb,
                        const float* __restrict__ wb, int* __restrict__ cntb,
                        const int* __restrict__ offb, ull* __restrict__ epack) {
    int t = blockIdx.y;
    int e = blockIdx.x * blockDim.x + threadIdx.x;
    if (e >= EE) return;
    int d = dstb[(size_t)t * EE + e];
    int p = offb[t * (NN + 1) + d] + atomicAdd(&cntb[t * NN + d], 1);
    ull pk = ((ull)__float_as_uint(wb[(size_t)t * EE + e]) << 32) |
             (ull)(unsigned)srcb[(size_t)t * EE + e];
    epack[(size_t)t * EE + p] = pk;
}

// ---------------- SpMM (batched over T) + fused layer1 scores ----------------
__global__ void k_spmm128(const float* __restrict__ XWb,
                          const ull* __restrict__ epb,
                          const int* __restrict__ offb, float* __restrict__ outb,
                          const float* __restrict__ scorer,
                          const float* __restrict__ snormp,
                          const float* __restrict__ maskb,
                          float* __restrict__ scores, unsigned* __restrict__ hist,
                          int slot0) {
    int t = blockIdx.y;
    int slot = slot0 + t;
    const float4* X4 = (const float4*)(XWb + (size_t)t * NN * 128);
    const ull* ep = epb + (size_t)t * EE;
    const int* off = offb + t * (NN + 1);
    float* out = outb + (size_t)t * NN * 128;
    int gt = blockIdx.x * blockDim.x + threadIdx.x;
    int n = gt >> 5, lane = gt & 31;
    if (n >= NN) return;
    int beg = off[n], end = off[n + 1];
    float4 a0 = make_float4(0.f, 0.f, 0.f, 0.f);
    float4 a1 = a0, a2 = a0, a3 = a0;
    int j = beg;
    for (; j + 4 <= end; j += 4) {
        ull e0 = __ldg(ep + j), e1 = __ldg(ep + j + 1);
        ull e2 = __ldg(ep + j + 2), e3 = __ldg(ep + j + 3);
        int s0 = (int)(unsigned)e0, s1 = (int)(unsigned)e1;
        int s2 = (int)(unsigned)e2, s3 = (int)(unsigned)e3;
        float w0 = __uint_as_float((unsigned)(e0 >> 32));
        float w1 = __uint_as_float((unsigned)(e1 >> 32));
        float w2 = __uint_as_float((unsigned)(e2 >> 32));
        float w3 = __uint_as_float((unsigned)(e3 >> 32));
        float4 v0 = __ldg(&X4[(size_t)s0 * 32 + lane]);
        float4 v1 = __ldg(&X4[(size_t)s1 * 32 + lane]);
        float4 v2 = __ldg(&X4[(size_t)s2 * 32 + lane]);
        float4 v3 = __ldg(&X4[(size_t)s3 * 32 + lane]);
        a0.x += v0.x * w0; a0.y += v0.y * w0; a0.z += v0.z * w0; a0.w += v0.w * w0;
        a1.x += v1.x * w1; a1.y += v1.y * w1; a1.z += v1.z * w1; a1.w += v1.w * w1;
        a2.x += v2.x * w2; a2.y += v2.y * w2; a2.z += v2.z * w2; a2.w += v2.w * w2;
        a3.x += v3.x * w3; a3.y += v3.y * w3; a3.z += v3.z * w3; a3.w += v3.w * w3;
    }
    for (; j < end; ++j) {
        ull e0 = __ldg(ep + j);
        int s = (int)(unsigned)e0;
        float wt = __uint_as_float((unsigned)(e0 >> 32));
        float4 v = __ldg(&X4[(size_t)s * 32 + lane]);
        a0.x += v.x * wt; a0.y += v.y * wt; a0.z += v.z * wt; a0.w += v.w * wt;
    }
    float4 a = make_float4((a0.x + a1.x) + (a2.x + a3.x), (a0.y + a1.y) + (a2.y + a3.y),
                           (a0.z + a1.z) + (a2.z + a3.z), (a0.w + a1.w) + (a2.w + a3.w));
    float4 r = make_float4(fmaxf(a.x, 0.f), fmaxf(a.y, 0.f), fmaxf(a.z, 0.f), fmaxf(a.w, 0.f));
    ((float4*)out)[(size_t)n * 32 + lane] = r;
    float4 sc4 = __ldg(&((const float4*)scorer)[lane]);
    float sc = r.x * sc4.x + r.y * sc4.y + r.z * sc4.z + r.w * sc4.w;
#pragma unroll
    for (int o = 16; o; o >>= 1) sc += __shfl_xor_sync(0xffffffffu, sc, o);
    if (lane == 0) {
        float s = sc / (*snormp) + maskb[(size_t)t * NN + n];
        scores[slot * NN + n] = s;
        int cp = blockIdx.x & (NCOPY - 1);
        atomicAdd(&hist[slot * NCOPY * 4096 + cp * 4096 + (mono(s) >> 20)], 1u);
    }
}

__global__ void k_spmm64(const float* __restrict__ XWb, const ull* __restrict__ epb,
                         const int* __restrict__ offb, float* __restrict__ outb) {
    int t = blockIdx.y;
    const float2* X2 = (const float2*)(XWb + (size_t)t * NN * 64);
    const ull* ep = epb + (size_t)t * EE;
    const int* off = offb + t * (NN + 1);
    float* out = outb + (size_t)t * NN * 64;
    int gt = blockIdx.x * blockDim.x + threadIdx.x;
    int n = gt >> 5, lane = gt & 31;
    if (n >= NN) return;
    int beg = off[n], end = off[n + 1];
    float2 a0 = make_float2(0.f, 0.f), a1 = a0, a2 = a0, a3 = a0;
    int j = beg;
    for (; j + 4 <= end; j += 4) {
        ull e0 = __ldg(ep + j), e1 = __ldg(ep + j + 1);
        ull e2 = __ldg(ep + j + 2), e3 = __ldg(ep + j + 3);
        int s0 = (int)(unsigned)e0, s1 = (int)(unsigned)e1;
        int s2 = (int)(unsigned)e2, s3 = (int)(unsigned)e3;
        float w0 = __uint_as_float((unsigned)(e0 >> 32));
        float w1 = __uint_as_float((unsigned)(e1 >> 32));
        float w2 = __uint_as_float((unsigned)(e2 >> 32));
        float w3 = __uint_as_float((unsigned)(e3 >> 32));
        float2 v0 = __ldg(&X2[(size_t)s0 * 32 + lane]);
        float2 v1 = __ldg(&X2[(size_t)s1 * 32 + lane]);
        float2 v2 = __ldg(&X2[(size_t)s2 * 32 + lane]);
        float2 v3 = __ldg(&X2[(size_t)s3 * 32 + lane]);
        a0.x += v0.x * w0; a0.y += v0.y * w0;
        a1.x += v1.x * w1; a1.y += v1.y * w1;
        a2.x += v2.x * w2; a2.y += v2.y * w2;
        a3.x += v3.x * w3; a3.y += v3.y * w3;
    }
    for (; j < end; ++j) {
        ull e0 = __ldg(ep + j);
        int s = (int)(unsigned)e0;
        float wt = __uint_as_float((unsigned)(e0 >> 32));
        float2 v = __ldg(&X2[(size_t)s * 32 + lane]);
        a0.x += v.x * wt; a0.y += v.y * wt;
    }
    float2 a = make_float2((a0.x + a1.x) + (a2.x + a3.x), (a0.y + a1.y) + (a2.y + a3.y));
    ((float2*)out)[(size_t)n * 32 + lane] = make_float2(fmaxf(a.x, 0.f), fmaxf(a.y, 0.f));
}

// ---------------- host orchestration ----------------
extern "C" void kernel_launch(void* const* d_in, const int* in_sizes, int n_in,
                              void* d_out, int out_size) {
    const float* node_embs = (const float*)d_in[0];
    const float* mask = (const float*)d_in[1];
    const int* esrc = (const int*)d_in[2];
    const int* edst = (const int*)d_in[3];
    const float* ew = (const float*)d_in[4];
    const float* w0 = (const float*)d_in[5];
    const float* w1 = (const float*)d_in[6];
    const float* p0[10];
    const float* p1[10];
    for (int i = 0; i < 10; i++) p0[i] = (const float*)d_in[7 + i];
    for (int i = 0; i < 10; i++) p1[i] = (const float*)d_in[17 + i];
    float* out = (float*)d_out;

    float *XW0, *X1, *XW1, *scores, *ttanh, *zT, *Q0s, *Q1s, *snorm;
    unsigned* hist;
    int *ctrl, *tidx, *cnt, *off, *bsum;
    ull *cand, *epack;
    cudaGetSymbolAddress((void**)&XW0, g_XW0);
    cudaGetSymbolAddress((void**)&X1, g_X1);
    cudaGetSymbolAddress((void**)&XW1, g_XW1);
    cudaGetSymbolAddress((void**)&scores, g_scores);
    cudaGetSymbolAddress((void**)&hist, g_hist);
    cudaGetSymbolAddress((void**)&ctrl, g_ctrl);
    cudaGetSymbolAddress((void**)&cand, g_cand);
    cudaGetSymbolAddress((void**)&tidx, g_tidx);
    cudaGetSymbolAddress((void**)&ttanh, g_ttanh);
    cudaGetSymbolAddress((void**)&zT, g_zT);
    cudaGetSymbolAddress((void**)&Q0s, g_Q0snap);
    cudaGetSymbolAddress((void**)&Q1s, g_Q1snap);
    cudaGetSymbolAddress((void**)&snorm, g_snorm);
    cudaGetSymbolAddress((void**)&cnt, g_cnt);
    cudaGetSymbolAddress((void**)&off, g_off);
    cudaGetSymbolAddress((void**)&bsum, g_bsum);
    cudaGetSymbolAddress((void**)&epack, g_epack);

    const int NBLK = (NN + 255) / 256;
    const int WBLK = (NN * 32 + 255) / 256;
    const int EBLK = (EE + 255) / 256;
    const int GBLK = (NN + 127) / 128;
    const int ZBLK = (NSLOT * NCOPY * 4096 + 255) / 256;

    k_snorm<<<2, 128>>>(p0[9], p1[9], snorm);
    k_zeroall<<<ZBLK, 256>>>(hist, ctrl, cnt);
    k_histdst<<<dim3(EBLK, TT), 256>>>(edst, cnt);
    k_scoreshist<<<dim3(WBLK, TT), 256>>>(node_embs, mask, p0[9], snorm + 0, scores, hist);
    k_scan1<<<dim3(SBLK, TT), 256>>>(cnt, off, bsum);
    k_scan2<<<TT, 256>>>(bsum, off);
    k_scan3<<<dim3(SBLK, TT), 256>>>(off, bsum);
    k_place<<<dim3(EBLK, TT), 256>>>(esrc, edst, ew, cnt, off, epack);

    // layer0 top-k (slots 0..3)
    k_findbucket<<<TT, 1024>>>(hist, ctrl, 0, 128);
    k_compact<<<dim3(NBLK, TT), 256>>>(scores, ctrl, cand, 0);
    k_sortselect<<<TT, 1024>>>(scores, cand, ctrl, tidx, ttanh, 0, 128);
    k_buildz<<<dim3(128, TT), 128>>>(node_embs, tidx, ttanh, zT, 0);

    // layer0 GRU: all t fused, coalesced (4 blocks of 32 columns)
    k_gruallc<128><<<4, 1024>>>(p0[0], p0[1], p0[2], p0[3], p0[4], p0[5], p0[6], p0[7],
                                p0[8], zT, w0, Q0s);

    // layer0 GEMM + SpMM (batched over T) with fused layer1 scores
    k_gemmcf<128><<<dim3(GBLK, TT), 256>>>(node_embs, (size_t)NN * 128, Q0s, 16384, XW0,
                                           (size_t)NN * 128);
    k_spmm128<<<dim3(WBLK, TT), 256>>>(XW0, epack, off, X1, p1[9], snorm + 1, mask,
                                       scores, hist, 4);

    // layer1 top-k (slots 4..7)
    k_findbucket<<<TT, 1024>>>(hist, ctrl, 4, 64);
    k_compact<<<dim3(NBLK, TT), 256>>>(scores, ctrl, cand, 4);
    k_sortselect<<<TT, 1024>>>(scores, cand, ctrl, tidx, ttanh, 4, 64);
    k_buildz<<<dim3(64, TT), 128>>>(X1, tidx, ttanh, zT, 4);

    // layer1 GRU: all t fused, coalesced (2 blocks of 32 columns)
    k_gruallc<64><<<2, 1024>>>(p1[0], p1[1], p1[2], p1[3], p1[4], p1[5], p1[6], p1[7],
                               p1[8], zT + 4 * 16384, w1, Q1s);

    // layer1 GEMM + SpMM (batched over T)
    k_gemmcf<64><<<dim3(GBLK, TT), 256>>>(X1, (size_t)NN * 128, Q1s, 8192, XW1,
                                          (size_t)NN * 64);
    k_spmm64<<<dim3(WBLK, TT), 256>>>(XW1, epack, off, out);
}

// round 17
// speedup vs baseline: 1.5074x; 1.4941x over previous
#include <cuda_runtime.h>
#include <math.h>

#define TT 4
#define NN 50000
#define EE 400000
#define CAP 2048
#define NSLOT 8
#define NCOPY 8
#define SBLK 196   // scan blocks per t (196*256 >= NN)

typedef unsigned long long ull;

// ---------------- scratch ----------------
__device__ float g_XW0[TT * NN * 128];
__device__ float g_X1[TT * NN * 128];
__device__ float g_XW1[TT * NN * 64];
__device__ float g_scores[NSLOT * NN];
__device__ unsigned g_hist[NSLOT * NCOPY * 4096];
__device__ int g_ctrl[NSLOT * 4];
__device__ ull g_cand[NSLOT * CAP];
__device__ int g_tidx[NSLOT * 128];
__device__ float g_ttanh[NSLOT * 128];
__device__ float g_zT[NSLOT * 128 * 128];   // zT[slot][i][c] (transposed)
__device__ float g_Q0snap[TT * 128 * 128];
__device__ float g_Q1snap[TT * 128 * 64];
__device__ float g_upd[128 * 128];
__device__ float g_rstq[128 * 128];
__device__ float g_snorm[2];
__device__ int g_cnt[TT * NN];
__device__ int g_off[TT * (NN + 1)];
__device__ int g_bsum[TT * SBLK];
__device__ ull g_epack[TT * EE];   // packed (weight_bits<<32 | src)

__device__ __forceinline__ unsigned mono(float f) {
    unsigned u = __float_as_uint(f);
    return (u & 0x80000000u) ? ~u : (u | 0x80000000u);
}
__device__ __forceinline__ float sigm(float x) { return 1.f / (1.f + expf(-x)); }
__device__ __forceinline__ ull fdup(float v) {
    ull r; asm("mov.b64 %0, {%1,%2};" : "=l"(r) : "f"(v), "f"(v)); return r;
}
__device__ __forceinline__ void ffma2(ull& d, ull a, ull b) {
    asm("fma.rn.f32x2 %0, %1, %2, %3;" : "=l"(d) : "l"(a), "l"(b), "l"(d));
}
__device__ __forceinline__ float2 up2(ull v) {
    float2 f; asm("mov.b64 {%0,%1}, %2;" : "=f"(f.x), "=f"(f.y) : "l"(v)); return f;
}

// ---------------- init ----------------
__global__ void k_snorm(const float* __restrict__ s0, const float* __restrict__ s1,
                        float* out) {
    __shared__ float sh[128];
    const float* sc = blockIdx.x ? s1 : s0;
    int t = threadIdx.x;
    float v = sc[t];
    sh[t] = v * v;
    __syncthreads();
    for (int o = 64; o > 0; o >>= 1) {
        if (t < o) sh[t] += sh[t + o];
        __syncthreads();
    }
    if (t == 0) out[blockIdx.x] = sqrtf(sh[0]);
}

__global__ void k_zeroall(unsigned* hist, int* ctrl, int* cnt) {
    int i = blockIdx.x * blockDim.x + threadIdx.x;
    if (i < NSLOT * NCOPY * 4096) hist[i] = 0u;
    if (i < NSLOT * 4) ctrl[i] = 0;
    if (i < TT * NN) cnt[i] = 0;
}

// ---------------- scores + replicated histogram (layer0) ----------------
__global__ void k_scoreshist(const float* __restrict__ Xb,
                             const float* __restrict__ maskb,
                             const float* __restrict__ scorer,
                             const float* __restrict__ snormp,
                             float* __restrict__ scores, unsigned* __restrict__ hist) {
    int slot = blockIdx.y;
    const float4* X4 = (const float4*)(Xb + (size_t)slot * NN * 128);
    const float* m = maskb + (size_t)slot * NN;
    int gt = blockIdx.x * blockDim.x + threadIdx.x;
    int n = gt >> 5, lane = gt & 31;
    if (n >= NN) return;
    float4 x = __ldg(&X4[(size_t)n * 32 + lane]);
    float4 s4 = __ldg(&((const float4*)scorer)[lane]);
    float acc = x.x * s4.x + x.y * s4.y + x.z * s4.z + x.w * s4.w;
#pragma unroll
    for (int o = 16; o; o >>= 1) acc += __shfl_xor_sync(0xffffffffu, acc, o);
    if (lane == 0) {
        float s = acc / (*snormp) + m[n];
        scores[slot * NN + n] = s;
        int cp = blockIdx.x & (NCOPY - 1);
        atomicAdd(&hist[slot * NCOPY * 4096 + cp * 4096 + (mono(s) >> 20)], 1u);
    }
}

// findbucket: sums NCOPY replicated histograms per bucket
__global__ void k_findbucket(const unsigned* __restrict__ hist, int* __restrict__ ctrl,
                             int slot0, int k) {
    __shared__ unsigned sh[1024];
    int slot = slot0 + blockIdx.x;
    const unsigned* h = hist + (size_t)slot * NCOPY * 4096;
    int tid = threadIdx.x;
    int c0 = tid * 4;
    unsigned h0 = 0, h1 = 0, h2 = 0, h3 = 0;
#pragma unroll
    for (int cp = 0; cp < NCOPY; cp++) {
        const unsigned* hc = h + cp * 4096;
        h0 += hc[c0]; h1 += hc[c0 + 1]; h2 += hc[c0 + 2]; h3 += hc[c0 + 3];
    }
    sh[tid] = h0 + h1 + h2 + h3;
    __syncthreads();
    for (int o = 1; o < 1024; o <<= 1) {
        unsigned v = (tid + o < 1024) ? sh[tid + o] : 0u;
        __syncthreads();
        sh[tid] += v;
        __syncthreads();
    }
    unsigned above = (tid < 1023) ? sh[tid + 1] : 0u;
    unsigned hh[4] = {h0, h1, h2, h3};
    for (int b = 3; b >= 0; --b) {
        unsigned cnt = hh[b];
        if (above < (unsigned)k && above + cnt >= (unsigned)k) ctrl[slot * 4 + 0] = c0 + b;
        above += cnt;
    }
}

__global__ void k_compact(const float* __restrict__ scores, int* __restrict__ ctrl,
                          ull* __restrict__ cand, int slot0) {
    int slot = slot0 + blockIdx.y;
    int bstar = ctrl[slot * 4 + 0];
    int i = blockIdx.x * blockDim.x + threadIdx.x;
    if (i >= NN) return;
    unsigned key = mono(scores[slot * NN + i]);
    if ((int)(key >> 20) >= bstar) {
        int p = atomicAdd(&ctrl[slot * 4 + 2], 1);
        if (p < CAP)
            cand[slot * CAP + p] = ((ull)key << 32) | (ull)(0xFFFFFFFFu - (unsigned)i);
    }
}

__global__ void k_sortselect(const float* __restrict__ scores, const ull* __restrict__ cand,
                             const int* __restrict__ ctrl, int* __restrict__ tidx,
                             float* __restrict__ ttanh, int slot0, int k) {
    __shared__ ull s[CAP];
    int slot = slot0 + blockIdx.x;
    int tid = threadIdx.x;
    int n = ctrl[slot * 4 + 2];
    if (n > CAP) n = CAP;
    for (int i = tid; i < CAP; i += 1024) s[i] = (i < n) ? cand[slot * CAP + i] : 0ULL;
    __syncthreads();
    for (int size = 2; size <= CAP; size <<= 1)
        for (int stride = size >> 1; stride > 0; stride >>= 1) {
            for (int i = tid; i < CAP; i += 1024) {
                int j = i ^ stride;
                if (j > i) {
                    ull a = s[i], b = s[j];
                    bool desc = ((i & size) == 0);
                    if (desc ? (a < b) : (a > b)) { s[i] = b; s[j] = a; }
                }
            }
            __syncthreads();
        }
    if (tid < k) {
        ull c = s[tid];
        unsigned idx = 0xFFFFFFFFu - (unsigned)(c & 0xFFFFFFFFu);
        tidx[slot * 128 + tid] = (int)idx;
        ttanh[slot * 128 + tid] = tanhf(scores[slot * NN + idx]);
    }
}

// buildz: writes TRANSPOSED z: zT[slot][r][j], r=thread, j=block (COLS=gridDim.x)
__global__ void k_buildz(const float* __restrict__ Xb,
                         const int* __restrict__ tidx, const float* __restrict__ ttanh,
                         float* __restrict__ zT, int slot0) {
    int by = blockIdx.y;
    int slot = slot0 + by;
    const float* X = Xb + (size_t)by * NN * 128;
    int j = blockIdx.x, r = threadIdx.x;
    int COLS = gridDim.x;
    zT[slot * 16384 + r * COLS + j] =
        X[(size_t)tidx[slot * 128 + j] * 128 + r] * ttanh[slot * 128 + j];
}

// ---------------- GRU per-t, coalesced (W broadcast, zT/Q/rstq lane-contiguous) ----------------
__global__ void k_gru1(const float* __restrict__ Wu, const float* __restrict__ Uu,
                       const float* __restrict__ Bu, const float* __restrict__ Wr,
                       const float* __restrict__ Ur, const float* __restrict__ Br,
                       const float* __restrict__ zT, const float* __restrict__ Q,
                       float* __restrict__ upd, float* __restrict__ rstq, int COLS) {
    int idx = blockIdx.x * blockDim.x + threadIdx.x;
    if (idx >= 128 * COLS) return;
    int c = idx % COLS, r = idx / COLS;
    float su = 0, sr = 0, qu = 0, qr = 0;
#pragma unroll 4
    for (int i = 0; i < 128; i++) {
        float zi = __ldg(&zT[i * COLS + c]);
        float qi = __ldg(&Q[i * COLS + c]);
        float wu = __ldg(&Wu[r * 128 + i]);
        float wr = __ldg(&Wr[r * 128 + i]);
        float uu = __ldg(&Uu[r * 128 + i]);
        float ur = __ldg(&Ur[r * 128 + i]);
        su += wu * zi;
        sr += wr * zi;
        qu += uu * qi;
        qr += ur * qi;
    }
    float u = sigm(su + qu + Bu[r * COLS + c]);
    float rs = sigm(sr + qr + Br[r * COLS + c]);
    upd[r * COLS + c] = u;
    rstq[r * COLS + c] = rs * __ldg(&Q[r * COLS + c]);
}

__global__ void k_gru2(const float* __restrict__ Wh, const float* __restrict__ Uh,
                       const float* __restrict__ Bh, const float* __restrict__ zT,
                       const float* __restrict__ Qprev, float* __restrict__ Qnext,
                       const float* __restrict__ upd, const float* __restrict__ rstq,
                       int COLS) {
    int idx = blockIdx.x * blockDim.x + threadIdx.x;
    if (idx >= 128 * COLS) return;
    int c = idx % COLS, r = idx / COLS;
    float h = 0;
#pragma unroll 4
    for (int i = 0; i < 128; i++) {
        float wh = __ldg(&Wh[r * 128 + i]);
        float uh = __ldg(&Uh[r * 128 + i]);
        h += wh * __ldg(&zT[i * COLS + c]);
        h += uh * __ldg(&rstq[i * COLS + c]);
    }
    float hc = tanhf(h + Bh[r * COLS + c]);
    float u = upd[r * COLS + c];
    float q = __ldg(&Qprev[r * COLS + c]);
    Qnext[r * COLS + c] = (1.f - u) * q + u * hc;
}

// ---------------- SGEMM (f32x2, conflict-free strided micro-tile) ----------------
template <int BN>
__device__ __forceinline__ void gemm_tile(const float* __restrict__ A, bool aok, int lr,
                                          int lk, const float* __restrict__ B,
                                          float* __restrict__ C, int row0, int tx, int ty,
                                          float* As_f, ull* Bs, int tid) {
    constexpr int TN = BN / 16;
    ull* As = (ull*)As_f;
    ull acc[4][TN];
#pragma unroll
    for (int mp = 0; mp < 4; mp++)
#pragma unroll
        for (int n = 0; n < TN; n++) acc[mp][n] = 0ULL;
    const float4 z4 = make_float4(0.f, 0.f, 0.f, 0.f);
    int kb = tid >> 4, jj = tid & 15;
    for (int kt = 0; kt < 8; kt++) {
        float4 a0 = aok ? *(const float4*)(A + (size_t)(row0 + lr) * 128 + kt * 16 + lk) : z4;
        float4 a1 = aok ? *(const float4*)(A + (size_t)(row0 + lr) * 128 + kt * 16 + lk + 4) : z4;
        float av[8] = {a0.x, a0.y, a0.z, a0.w, a1.x, a1.y, a1.z, a1.w};
#pragma unroll
        for (int q = 0; q < 8; q++) As_f[(lk + q) * 128 + lr] = av[q];
#pragma unroll
        for (int i = 0; i < TN; i++) {
            float bv = B[(size_t)(kt * 16 + kb) * BN + jj + 16 * i];
            Bs[kb * BN + jj + 16 * i] = fdup(bv);
        }
        __syncthreads();
#pragma unroll
        for (int kk = 0; kk < 16; kk++) {
            ull a[4], rb[TN];
#pragma unroll
            for (int mp = 0; mp < 4; mp++) a[mp] = As[kk * 64 + ty + 16 * mp];
#pragma unroll
            for (int n = 0; n < TN; n++) rb[n] = Bs[kk * BN + tx + 16 * n];
#pragma unroll
            for (int mp = 0; mp < 4; mp++)
#pragma unroll
                for (int n = 0; n < TN; n++) ffma2(acc[mp][n], a[mp], rb[n]);
        }
        __syncthreads();
    }
#pragma unroll
    for (int mp = 0; mp < 4; mp++) {
        int r = row0 + 2 * (ty + 16 * mp);
        if (r >= NN) continue;
#pragma unroll
        for (int n = 0; n < TN; n++) {
            float2 p = up2(acc[mp][n]);
            C[(size_t)r * BN + tx + 16 * n] = p.x;
            C[(size_t)(r + 1) * BN + tx + 16 * n] = p.y;
        }
    }
}

template <int BN>
__global__ void __launch_bounds__(256) k_gemmcf(const float* __restrict__ Ab, size_t astr,
                                                const float* __restrict__ Bb, size_t bstr,
                                                float* __restrict__ Cb, size_t cstr) {
    __shared__ float As_f[16 * 128];
    __shared__ ull Bs[16 * BN];
    const float* A = Ab + (size_t)blockIdx.y * astr;
    const float* B = Bb + (size_t)blockIdx.y * bstr;
    float* C = Cb + (size_t)blockIdx.y * cstr;
    int tid = threadIdx.x, tx = tid & 15, ty = tid >> 4;
    int row0 = blockIdx.x * 128;
    int lr = tid >> 1, lk = (tid & 1) * 8;
    bool aok = (row0 + lr) < NN;
    gemm_tile<BN>(A, aok, lr, lk, B, C, row0, tx, ty, As_f, Bs, tid);
}

// ---------------- CSR build ----------------
__global__ void k_histdst(const int* __restrict__ dstb, int* __restrict__ cnt) {
    int t = blockIdx.y;
    int e = blockIdx.x * blockDim.x + threadIdx.x;
    if (e < EE) atomicAdd(&cnt[t * NN + dstb[(size_t)t * EE + e]], 1);
}

__global__ void k_scan1(int* __restrict__ cnt, int* __restrict__ off,
                        int* __restrict__ bsum) {
    __shared__ int ws[8];
    int t = blockIdx.y, b = blockIdx.x;
    int tid = threadIdx.x, lane = tid & 31, wid = tid >> 5;
    int i = b * 256 + tid;
    int c = (i < NN) ? cnt[t * NN + i] : 0;
    if (i < NN) cnt[t * NN + i] = 0;
    int v = c;
#pragma unroll
    for (int o = 1; o < 32; o <<= 1) {
        int nv = __shfl_up_sync(0xffffffffu, v, o);
        if (lane >= o) v += nv;
    }
    if (lane == 31) ws[wid] = v;
    __syncthreads();
    if (wid == 0 && lane < 8) {
        int w = ws[lane];
#pragma unroll
        for (int o = 1; o < 8; o <<= 1) {
            int nw = __shfl_up_sync(0xFFu, w, o);
            if (lane >= o) w += nw;
        }
        ws[lane] = w;
    }
    __syncthreads();
    int ex = v - c + (wid ? ws[wid - 1] : 0);
    if (i < NN) off[t * (NN + 1) + i] = ex;
    if (tid == 255) bsum[t * SBLK + b] = ex + c;
}

__global__ void k_scan2(int* __restrict__ bsum, int* __restrict__ off) {
    __shared__ int ws[8];
    int t = blockIdx.x;
    int tid = threadIdx.x, lane = tid & 31, wid = tid >> 5;
    int c = (tid < SBLK) ? bsum[t * SBLK + tid] : 0;
    int v = c;
#pragma unroll
    for (int o = 1; o < 32; o <<= 1) {
        int nv = __shfl_up_sync(0xffffffffu, v, o);
        if (lane >= o) v += nv;
    }
    if (lane == 31) ws[wid] = v;
    __syncthreads();
    if (wid == 0 && lane < 8) {
        int w = ws[lane];
#pragma unroll
        for (int o = 1; o < 8; o <<= 1) {
            int nw = __shfl_up_sync(0xFFu, w, o);
            if (lane >= o) w += nw;
        }
        ws[lane] = w;
    }
    __syncthreads();
    int ex = v - c + (wid ? ws[wid - 1] : 0);
    if (tid < SBLK) bsum[t * SBLK + tid] = ex;
    if (tid == SBLK - 1) off[t * (NN + 1) + NN] = ex + c;
}

__global__ void k_scan3(int* __restrict__ off, const int* __restrict__ bsum) {
    int t = blockIdx.y, b = blockIdx.x;
    int i = b * 256 + threadIdx.x;
    if (i < NN) off[t * (NN + 1) + i] += bsum[t * SBLK + b];
}

// place: ONE packed 8B scatter per edge
__global__ void k_place(const int* __restrict__ srcb, const int* __restrict__ dstb,
                        const float* __restrict__ wb, int* __restrict__ cntb,
                        const int* __restrict__ offb, ull* __restrict__ epack) {
    int t = blockIdx.y;
    int e = blockIdx.x * blockDim.x + threadIdx.x;
    if (e >= EE) return;
    int d = dstb[(size_t)t * EE + e];
    int p = offb[t * (NN + 1) + d] + atomicAdd(&cntb[t * NN + d], 1);
    ull pk = ((ull)__float_as_uint(wb[(size_t)t * EE + e]) << 32) |
             (ull)(unsigned)srcb[(size_t)t * EE + e];
    epack[(size_t)t * EE + p] = pk;
}

// ---------------- SpMM (batched over T) + fused layer1 scores ----------------
__global__ void k_spmm128(const float* __restrict__ XWb,
                          const ull* __restrict__ epb,
                          const int* __restrict__ offb, float* __restrict__ outb,
                          const float* __restrict__ scorer,
                          const float* __restrict__ snormp,
                          const float* __restrict__ maskb,
                          float* __restrict__ scores, unsigned* __restrict__ hist,
                          int slot0) {
    int t = blockIdx.y;
    int slot = slot0 + t;
    const float4* X4 = (const float4*)(XWb + (size_t)t * NN * 128);
    const ull* ep = epb + (size_t)t * EE;
    const int* off = offb + t * (NN + 1);
    float* out = outb + (size_t)t * NN * 128;
    int gt = blockIdx.x * blockDim.x + threadIdx.x;
    int n = gt >> 5, lane = gt & 31;
    if (n >= NN) return;
    int beg = off[n], end = off[n + 1];
    float4 a0 = make_float4(0.f, 0.f, 0.f, 0.f);
    float4 a1 = a0, a2 = a0, a3 = a0;
    int j = beg;
    for (; j + 4 <= end; j += 4) {
        ull e0 = __ldg(ep + j), e1 = __ldg(ep + j + 1);
        ull e2 = __ldg(ep + j + 2), e3 = __ldg(ep + j + 3);
        int s0 = (int)(unsigned)e0, s1 = (int)(unsigned)e1;
        int s2 = (int)(unsigned)e2, s3 = (int)(unsigned)e3;
        float w0 = __uint_as_float((unsigned)(e0 >> 32));
        float w1 = __uint_as_float((unsigned)(e1 >> 32));
        float w2 = __uint_as_float((unsigned)(e2 >> 32));
        float w3 = __uint_as_float((unsigned)(e3 >> 32));
        float4 v0 = __ldg(&X4[(size_t)s0 * 32 + lane]);
        float4 v1 = __ldg(&X4[(size_t)s1 * 32 + lane]);
        float4 v2 = __ldg(&X4[(size_t)s2 * 32 + lane]);
        float4 v3 = __ldg(&X4[(size_t)s3 * 32 + lane]);
        a0.x += v0.x * w0; a0.y += v0.y * w0; a0.z += v0.z * w0; a0.w += v0.w * w0;
        a1.x += v1.x * w1; a1.y += v1.y * w1; a1.z += v1.z * w1; a1.w += v1.w * w1;
        a2.x += v2.x * w2; a2.y += v2.y * w2; a2.z += v2.z * w2; a2.w += v2.w * w2;
        a3.x += v3.x * w3; a3.y += v3.y * w3; a3.z += v3.z * w3; a3.w += v3.w * w3;
    }
    for (; j < end; ++j) {
        ull e0 = __ldg(ep + j);
        int s = (int)(unsigned)e0;
        float wt = __uint_as_float((unsigned)(e0 >> 32));
        float4 v = __ldg(&X4[(size_t)s * 32 + lane]);
        a0.x += v.x * wt; a0.y += v.y * wt; a0.z += v.z * wt; a0.w += v.w * wt;
    }
    float4 a = make_float4((a0.x + a1.x) + (a2.x + a3.x), (a0.y + a1.y) + (a2.y + a3.y),
                           (a0.z + a1.z) + (a2.z + a3.z), (a0.w + a1.w) + (a2.w + a3.w));
    float4 r = make_float4(fmaxf(a.x, 0.f), fmaxf(a.y, 0.f), fmaxf(a.z, 0.f), fmaxf(a.w, 0.f));
    ((float4*)out)[(size_t)n * 32 + lane] = r;
    float4 sc4 = __ldg(&((const float4*)scorer)[lane]);
    float sc = r.x * sc4.x + r.y * sc4.y + r.z * sc4.z + r.w * sc4.w;
#pragma unroll
    for (int o = 16; o; o >>= 1) sc += __shfl_xor_sync(0xffffffffu, sc, o);
    if (lane == 0) {
        float s = sc / (*snormp) + maskb[(size_t)t * NN + n];
        scores[slot * NN + n] = s;
        int cp = blockIdx.x & (NCOPY - 1);
        atomicAdd(&hist[slot * NCOPY * 4096 + cp * 4096 + (mono(s) >> 20)], 1u);
    }
}

__global__ void k_spmm64(const float* __restrict__ XWb, const ull* __restrict__ epb,
                         const int* __restrict__ offb, float* __restrict__ outb) {
    int t = blockIdx.y;
    const float2* X2 = (const float2*)(XWb + (size_t)t * NN * 64);
    const ull* ep = epb + (size_t)t * EE;
    const int* off = offb + t * (NN + 1);
    float* out = outb + (size_t)t * NN * 64;
    int gt = blockIdx.x * blockDim.x + threadIdx.x;
    int n = gt >> 5, lane = gt & 31;
    if (n >= NN) return;
    int beg = off[n], end = off[n + 1];
    float2 a0 = make_float2(0.f, 0.f), a1 = a0, a2 = a0, a3 = a0;
    int j = beg;
    for (; j + 4 <= end; j += 4) {
        ull e0 = __ldg(ep + j), e1 = __ldg(ep + j + 1);
        ull e2 = __ldg(ep + j + 2), e3 = __ldg(ep + j + 3);
        int s0 = (int)(unsigned)e0, s1 = (int)(unsigned)e1;
        int s2 = (int)(unsigned)e2, s3 = (int)(unsigned)e3;
        float w0 = __uint_as_float((unsigned)(e0 >> 32));
        float w1 = __uint_as_float((unsigned)(e1 >> 32));
        float w2 = __uint_as_float((unsigned)(e2 >> 32));
        float w3 = __uint_as_float((unsigned)(e3 >> 32));
        float2 v0 = __ldg(&X2[(size_t)s0 * 32 + lane]);
        float2 v1 = __ldg(&X2[(size_t)s1 * 32 + lane]);
        float2 v2 = __ldg(&X2[(size_t)s2 * 32 + lane]);
        float2 v3 = __ldg(&X2[(size_t)s3 * 32 + lane]);
        a0.x += v0.x * w0; a0.y += v0.y * w0;
        a1.x += v1.x * w1; a1.y += v1.y * w1;
        a2.x += v2.x * w2; a2.y += v2.y * w2;
        a3.x += v3.x * w3; a3.y += v3.y * w3;
    }
    for (; j < end; ++j) {
        ull e0 = __ldg(ep + j);
        int s = (int)(unsigned)e0;
        float wt = __uint_as_float((unsigned)(e0 >> 32));
        float2 v = __ldg(&X2[(size_t)s * 32 + lane]);
        a0.x += v.x * wt; a0.y += v.y * wt;
    }
    float2 a = make_float2((a0.x + a1.x) + (a2.x + a3.x), (a0.y + a1.y) + (a2.y + a3.y));
    ((float2*)out)[(size_t)n * 32 + lane] = make_float2(fmaxf(a.x, 0.f), fmaxf(a.y, 0.f));
}

// ---------------- host orchestration ----------------
extern "C" void kernel_launch(void* const* d_in, const int* in_sizes, int n_in,
                              void* d_out, int out_size) {
    const float* node_embs = (const float*)d_in[0];
    const float* mask = (const float*)d_in[1];
    const int* esrc = (const int*)d_in[2];
    const int* edst = (const int*)d_in[3];
    const float* ew = (const float*)d_in[4];
    const float* w0 = (const float*)d_in[5];
    const float* w1 = (const float*)d_in[6];
    const float* p0[10];
    const float* p1[10];
    for (int i = 0; i < 10; i++) p0[i] = (const float*)d_in[7 + i];
    for (int i = 0; i < 10; i++) p1[i] = (const float*)d_in[17 + i];
    float* out = (float*)d_out;

    float *XW0, *X1, *XW1, *scores, *ttanh, *zT, *Q0s, *Q1s, *upd, *rstq, *snorm;
    unsigned* hist;
    int *ctrl, *tidx, *cnt, *off, *bsum;
    ull *cand, *epack;
    cudaGetSymbolAddress((void**)&XW0, g_XW0);
    cudaGetSymbolAddress((void**)&X1, g_X1);
    cudaGetSymbolAddress((void**)&XW1, g_XW1);
    cudaGetSymbolAddress((void**)&scores, g_scores);
    cudaGetSymbolAddress((void**)&hist, g_hist);
    cudaGetSymbolAddress((void**)&ctrl, g_ctrl);
    cudaGetSymbolAddress((void**)&cand, g_cand);
    cudaGetSymbolAddress((void**)&tidx, g_tidx);
    cudaGetSymbolAddress((void**)&ttanh, g_ttanh);
    cudaGetSymbolAddress((void**)&zT, g_zT);
    cudaGetSymbolAddress((void**)&Q0s, g_Q0snap);
    cudaGetSymbolAddress((void**)&Q1s, g_Q1snap);
    cudaGetSymbolAddress((void**)&upd, g_upd);
    cudaGetSymbolAddress((void**)&rstq, g_rstq);
    cudaGetSymbolAddress((void**)&snorm, g_snorm);
    cudaGetSymbolAddress((void**)&cnt, g_cnt);
    cudaGetSymbolAddress((void**)&off, g_off);
    cudaGetSymbolAddress((void**)&bsum, g_bsum);
    cudaGetSymbolAddress((void**)&epack, g_epack);

    // one-time resource init (no device memory; streams/events only)
    static cudaStream_t sB = nullptr;
    static cudaEvent_t evZ = nullptr, evB = nullptr;
    if (!sB) {
        cudaStreamCreateWithFlags(&sB, cudaStreamNonBlocking);
        cudaEventCreateWithFlags(&evZ, cudaEventDisableTiming);
        cudaEventCreateWithFlags(&evB, cudaEventDisableTiming);
    }

    const int NBLK = (NN + 255) / 256;
    const int WBLK = (NN * 32 + 255) / 256;
    const int EBLK = (EE + 255) / 256;
    const int GBLK = (NN + 127) / 128;
    const int ZBLK = (NSLOT * NCOPY * 4096 + 255) / 256;

    k_snorm<<<2, 128>>>(p0[9], p1[9], snorm);
    k_zeroall<<<ZBLK, 256>>>(hist, ctrl, cnt);

    // fork: CSR build on stream sB (independent of top-k/GRU/GEMM chain)
    cudaEventRecord(evZ, 0);
    cudaStreamWaitEvent(sB, evZ, 0);
    k_histdst<<<dim3(EBLK, TT), 256, 0, sB>>>(edst, cnt);
    k_scan1<<<dim3(SBLK, TT), 256, 0, sB>>>(cnt, off, bsum);
    k_scan2<<<TT, 256, 0, sB>>>(bsum, off);
    k_scan3<<<dim3(SBLK, TT), 256, 0, sB>>>(off, bsum);
    k_place<<<dim3(EBLK, TT), 256, 0, sB>>>(esrc, edst, ew, cnt, off, epack);
    cudaEventRecord(evB, sB);

    // main chain: layer0 top-k (slots 0..3) + GRU + GEMM
    k_scoreshist<<<dim3(WBLK, TT), 256>>>(node_embs, mask, p0[9], snorm + 0, scores, hist);
    k_findbucket<<<TT, 1024>>>(hist, ctrl, 0, 128);
    k_compact<<<dim3(NBLK, TT), 256>>>(scores, ctrl, cand, 0);
    k_sortselect<<<TT, 1024>>>(scores, cand, ctrl, tidx, ttanh, 0, 128);
    k_buildz<<<dim3(128, TT), 128>>>(node_embs, tidx, ttanh, zT, 0);

    for (int t = 0; t < TT; t++) {
        const float* Qp = t ? (Q0s + (t - 1) * 16384) : w0;
        k_gru1<<<64, 256>>>(p0[0], p0[1], p0[2], p0[3], p0[4], p0[5], zT + t * 16384, Qp,
                            upd, rstq, 128);
        k_gru2<<<64, 256>>>(p0[6], p0[7], p0[8], zT + t * 16384, Qp, Q0s + t * 16384,
                            upd, rstq, 128);
    }

    k_gemmcf<128><<<dim3(GBLK, TT), 256>>>(node_embs, (size_t)NN * 128, Q0s, 16384, XW0,
                                           (size_t)NN * 128);

    // join: SpMM needs CSR
    cudaStreamWaitEvent(0, evB, 0);
    k_spmm128<<<dim3(WBLK, TT), 256>>>(XW0, epack, off, X1, p1[9], snorm + 1, mask,
                                       scores, hist, 4);

    // layer1 top-k (slots 4..7)
    k_findbucket<<<TT, 1024>>>(hist, ctrl, 4, 64);
    k_compact<<<dim3(NBLK, TT), 256>>>(scores, ctrl, cand, 4);
    k_sortselect<<<TT, 1024>>>(scores, cand, ctrl, tidx, ttanh, 4, 64);
    k_buildz<<<dim3(64, TT), 128>>>(X1, tidx, ttanh, zT, 4);

    for (int t = 0; t < TT; t++) {
        const float* Qp = t ? (Q1s + (t - 1) * 8192) : w1;
        k_gru1<<<32, 256>>>(p1[0], p1[1], p1[2], p1[3], p1[4], p1[5], zT + (4 + t) * 16384,
                            Qp, upd, rstq, 64);
        k_gru2<<<32, 256>>>(p1[6], p1[7], p1[8], zT + (4 + t) * 16384, Qp, Q1s + t * 8192,
                            upd, rstq, 64);
    }

    k_gemmcf<64><<<dim3(GBLK, TT), 256>>>(X1, (size_t)NN * 128, Q1s, 8192, XW1,
                                          (size_t)NN * 64);
    k_spmm64<<<dim3(WBLK, TT), 256>>>(XW1, epack, off, out);
}